// round 13
// baseline (speedup 1.0000x reference)
#include <cuda_runtime.h>
#include <cstdint>
#include <cstddef>

#define Q      2048
#define NB2    64
#define NSTEP  32
#define NCTA   148
#define LP     68

// ---------------- scratch (device globals; no allocations allowed) ----------
__device__ float  g_A[Q*Q];                 // lower: working matrix; upper: L21^T
__device__ float  g_Linv[NSTEP*NB2*NB2];    // per-step inverse of diag block
__device__ float  g_w[Q];
__device__ int    g_cnt[Q];
__device__ float  g_v[Q];
__device__ double g_red[4];                 // [0]=m'm [1]=sum r^2 [2]=sum log Lkk
__device__ unsigned g_barCnt;               // monotonic grid-barrier counter

extern __shared__ float sh[];

// ---------------- grid barrier (R11 protocol: monotonic, acquire/release) ---
__device__ __forceinline__ void grid_bar(unsigned &target) {
  __threadfence();
  __syncthreads();
  if (threadIdx.x == 0) {
    target += NCTA;
    asm volatile("red.release.gpu.global.add.u32 [%0], 1;" :: "l"(&g_barCnt) : "memory");
    unsigned cur;
    do {
      asm volatile("ld.acquire.gpu.global.u32 %0, [%1];" : "=r"(cur) : "l"(&g_barCnt) : "memory");
    } while (cur < target);
  }
  __syncthreads();
  __threadfence();
}

__device__ __forceinline__ void team_bar(int team) {
  asm volatile("bar.sync %0, 128;" :: "r"(team + 4) : "memory");
}

__device__ __forceinline__ double block_reduce_512(double v, double* scratch) {
  #pragma unroll
  for (int o = 16; o; o >>= 1) v += __shfl_down_sync(0xffffffffu, v, o);
  if ((threadIdx.x & 31) == 0) scratch[threadIdx.x >> 5] = v;
  __syncthreads();
  double r = 0.0;
  if (threadIdx.x < 16) {
    r = scratch[threadIdx.x];
    #pragma unroll
    for (int o = 8; o; o >>= 1) r += __shfl_down_sync(0xffffu, r, o, 16);
  }
  __syncthreads();
  return r;   // valid on thread 0
}

// ---------------- reset kernel ----------------
__global__ void k_reset() {
  int i = blockIdx.x * blockDim.x + threadIdx.x;
  if (i < Q) { g_w[i] = 0.f; g_cnt[i] = 0; }
  if (i < 4) g_red[i] = 0.0;
  if (i == 0) g_barCnt = 0u;
}

// ---------------- 32x32 register factor + inverse (warp 0) ------------------
__device__ __forceinline__ void fact32(float* ds, float* li, float* lg,
                                       int base, int lane) {
  float a[32];
  #pragma unroll
  for (int j = 0; j < 32; j++) a[j] = ds[(base + lane) * LP + base + j];
  #pragma unroll
  for (int j = 0; j < 32; j++) {
    float dj  = __shfl_sync(0xffffffffu, a[j], j);
    float d   = sqrtf(dj);
    float inv = 1.f / d;
    if (lane == j)     a[j] = d;
    else if (lane > j) a[j] *= inv;
    float lj = a[j];
    #pragma unroll
    for (int k = j + 1; k < 32; k++) {
      float Lkj = __shfl_sync(0xffffffffu, a[j], k);
      if (lane >= k) a[k] -= lj * Lkj;
    }
  }
  #pragma unroll
  for (int j = 0; j < 32; j++)
    if (j <= lane) ds[(base + lane) * LP + base + j] = a[j];
  lg[base + lane] = logf(a[lane]);
  float dinvl = 1.f / a[lane];
  float x[32];
  #pragma unroll
  for (int r = 0; r < 32; r++) x[r] = (r == lane) ? 1.f : 0.f;
  #pragma unroll
  for (int k = 0; k < 32; k++) {
    float dk = __shfl_sync(0xffffffffu, dinvl, k);
    x[k] *= dk;
    float xk = x[k];
    #pragma unroll
    for (int r = k + 1; r < 32; r++) {
      float Lrk = __shfl_sync(0xffffffffu, a[k], r);
      x[r] -= Lrk * xk;
    }
  }
  #pragma unroll
  for (int r = 0; r < 32; r++)
    if (r >= lane) li[(base + r) * LP + base + lane] = x[r];
}

// ---------------- replicated 64x64 potf (every CTA) -------------------------
__device__ void potf64(float* ds, float* li, float* lg, int k0,
                       int tid, int warp, int lane) {
  for (int idx = tid; idx < 64 * 64; idx += 512) {
    int r = idx >> 6, c = idx & 63;
    ds[r * LP + c] = g_A[(size_t)(k0 + r) * Q + k0 + c];
    li[r * LP + c] = 0.f;
  }
  __syncthreads();

  if (warp == 0) fact32(ds, li, lg, 0, lane);
  __syncthreads();

  // X = B * M1^T  (B = ds[32:64,0:32]) in place
  bool act = tid < 64;
  int ti = tid >> 3, tj = tid & 7;
  int r0 = 32 + ti * 4, m0 = tj * 4;
  float xa[4][4] = {};
  if (act) {
    #pragma unroll
    for (int k = 0; k < 32; k++) {
      float b0 = ds[(r0 + 0) * LP + k], b1 = ds[(r0 + 1) * LP + k];
      float b2 = ds[(r0 + 2) * LP + k], b3 = ds[(r0 + 3) * LP + k];
      float m0v = li[(m0 + 0) * LP + k], m1v = li[(m0 + 1) * LP + k];
      float m2v = li[(m0 + 2) * LP + k], m3v = li[(m0 + 3) * LP + k];
      xa[0][0] += b0 * m0v; xa[0][1] += b0 * m1v; xa[0][2] += b0 * m2v; xa[0][3] += b0 * m3v;
      xa[1][0] += b1 * m0v; xa[1][1] += b1 * m1v; xa[1][2] += b1 * m2v; xa[1][3] += b1 * m3v;
      xa[2][0] += b2 * m0v; xa[2][1] += b2 * m1v; xa[2][2] += b2 * m2v; xa[2][3] += b2 * m3v;
      xa[3][0] += b3 * m0v; xa[3][1] += b3 * m1v; xa[3][2] += b3 * m2v; xa[3][3] += b3 * m3v;
    }
  }
  __syncthreads();
  if (act) {
    #pragma unroll
    for (int i = 0; i < 4; i++)
      #pragma unroll
      for (int j = 0; j < 4; j++)
        ds[(r0 + i) * LP + tj * 4 + j] = xa[i][j];
  }
  __syncthreads();

  // S22 -= X*X^T (lower 4x4 tiles)
  if (tid < 36) {
    int di = 0;
    while ((di + 1) * (di + 2) / 2 <= tid) di++;
    int dj = tid - di * (di + 1) / 2;
    int tr = 32 + di * 4, tc = 32 + dj * 4;
    float a2[4][4] = {};
    #pragma unroll
    for (int k = 0; k < 32; k++) {
      float a0 = ds[(tr + 0) * LP + k], a1 = ds[(tr + 1) * LP + k];
      float aa2 = ds[(tr + 2) * LP + k], a3 = ds[(tr + 3) * LP + k];
      float b0 = ds[(tc + 0) * LP + k], b1 = ds[(tc + 1) * LP + k];
      float b2 = ds[(tc + 2) * LP + k], b3 = ds[(tc + 3) * LP + k];
      a2[0][0] += a0 * b0; a2[0][1] += a0 * b1; a2[0][2] += a0 * b2; a2[0][3] += a0 * b3;
      a2[1][0] += a1 * b0; a2[1][1] += a1 * b1; a2[1][2] += a1 * b2; a2[1][3] += a1 * b3;
      a2[2][0] += aa2 * b0; a2[2][1] += aa2 * b1; a2[2][2] += aa2 * b2; a2[2][3] += aa2 * b3;
      a2[3][0] += a3 * b0; a2[3][1] += a3 * b1; a2[3][2] += a3 * b2; a2[3][3] += a3 * b3;
    }
    #pragma unroll
    for (int i = 0; i < 4; i++)
      #pragma unroll
      for (int j = 0; j < 4; j++)
        ds[(tr + i) * LP + tc + j] -= a2[i][j];
  }
  __syncthreads();

  if (warp == 0) fact32(ds, li, lg, 32, lane);
  __syncthreads();

  // T = L21 * M1 -> li[0:32, 32:64]
  for (int t = tid; t < 1024; t += 512) {
    int i = t >> 5, j = t & 31;
    float acc = 0.f;
    #pragma unroll 8
    for (int k = 0; k < 32; k++)
      acc += ds[(32 + i) * LP + k] * li[k * LP + j];
    li[i * LP + 32 + j] = acc;
  }
  __syncthreads();
  // M21 = -M2 * T -> li[32:64, 0:32]
  for (int t = tid; t < 1024; t += 512) {
    int i = t >> 5, j = t & 31;
    float acc = 0.f;
    #pragma unroll 8
    for (int k = 0; k < 32; k++)
      acc += li[(32 + i) * LP + 32 + k] * li[k * LP + 32 + j];
    li[(32 + i) * LP + j] = -acc;
  }
  __syncthreads();
  for (int t = tid; t < 1024; t += 512) {
    int i = t >> 5, j = t & 31;
    li[i * LP + 32 + j] = 0.f;
  }
  __syncthreads();
}

// ---------------- X = A21[rb] * Linv^T, stored TRANSPOSED in xt[k][r] --------
// If wb: also write L21^T into g_A upper (row k0+k, cols [r0,r0+64)).
__device__ __forceinline__ void compute_X(int k0, int rb, float* as, float* xt,
                                          const float* li, int wtid, int team,
                                          bool wb) {
  int r0 = k0 + NB2 + rb * 64;
  #pragma unroll 1
  for (int sb = 0; sb < 4; sb++) {
    int rbase = sb * 16;
    #pragma unroll
    for (int u = 0; u < 2; u++) {
      int t2 = wtid + u * 128;
      int r = t2 >> 4, c4 = t2 & 15;
      float4 va = *(const float4*)(g_A + (size_t)(r0 + rbase + r) * Q + k0 + c4 * 4);
      *(float4*)(as + r * LP + c4 * 4) = va;
    }
    team_bar(team);
    int row = wtid & 15, cg = wtid >> 4;
    float acc[8] = {};
    #pragma unroll
    for (int k4 = 0; k4 < 16; k4++) {
      float4 a4 = *(const float4*)(as + row * LP + k4 * 4);
      #pragma unroll
      for (int c = 0; c < 8; c++) {
        float4 m4 = *(const float4*)(li + (cg * 8 + c) * LP + k4 * 4);
        acc[c] += a4.x * m4.x + a4.y * m4.y + a4.z * m4.z + a4.w * m4.w;
      }
    }
    #pragma unroll
    for (int c = 0; c < 8; c++)
      xt[(cg * 8 + c) * LP + rbase + row] = acc[c];
    team_bar(team);
  }
  if (wb) {
    #pragma unroll
    for (int u = 0; u < 2; u++) {
      int t2 = wtid + u * 128;           // 256 jobs: 64 k x 4 chunks of 16
      int k = t2 >> 2, c4 = t2 & 3;
      const float* src = xt + k * LP + c4 * 16;
      float4 v0 = *(const float4*)(src);
      float4 v1 = *(const float4*)(src + 4);
      float4 v2 = *(const float4*)(src + 8);
      float4 v3 = *(const float4*)(src + 12);
      float* dst = g_A + (size_t)(k0 + k) * Q + r0 + c4 * 16;
      *(float4*)dst = v0; *(float4*)(dst + 4) = v1;
      *(float4*)(dst + 8) = v2; *(float4*)(dst + 12) = v3;
    }
  }
}

// ---------------- the one big persistent kernel ------------------------------
__global__ void __launch_bounds__(512, 1) k_chol(
    const float* __restrict__ yt, const float* __restrict__ yp,
    const int* __restrict__ z, const float* __restrict__ dist,
    const float* __restrict__ pe, const float* __restrict__ pb,
    const float* __restrict__ pl, float* __restrict__ out, int n) {
  int tid  = threadIdx.x;
  int warp = tid >> 5, lane = tid & 31;
  int team = tid >> 7, wtid = tid & 127;
  float* ds = sh;                         // 64*LP
  float* li = sh + 64 * LP;               // 64*LP
  float* lg = sh + 2 * 64 * LP;           // 64
  float* tb = sh + 2 * 64 * LP + 64;
  float* xi = tb + team * (2 * 64 * LP + 16 * LP);
  float* xj = xi + 64 * LP;
  float* as = xj + 64 * LP;
  unsigned bt = 0;

  // ---- phase 1: observations ----
  {
    double mm = 0.0, rr = 0.0;
    for (int i = blockIdx.x * 512 + tid; i < n; i += NCTA * 512) {
      float r = yt[i] - yp[i];
      float s2 = pe[0] + pb[0];
      float u  = 0.5f * (erff(r / sqrtf(2.f * s2)) + 1.f);
      u = fminf(fmaxf(u, 1e-5f), 1.f - 1e-5f);
      float m = erfinvf(2.f * u - 1.f) * 1.41421356237309515f;
      atomicAdd(&g_cnt[z[i]], 1);
      atomicAdd(&g_w[z[i]], m);
      mm += (double)m * (double)m;
      rr += (double)r * (double)r;
    }
    #pragma unroll
    for (int o = 16; o; o >>= 1) {
      mm += __shfl_down_sync(0xffffffffu, mm, o);
      rr += __shfl_down_sync(0xffffffffu, rr, o);
    }
    if (lane == 0) { atomicAdd(&g_red[0], mm); atomicAdd(&g_red[1], rr); }
  }
  grid_bar(bt);

  // ---- phase 2: build A + v ----
  {
    float inv2l = 0.5f / pl[0];
    float s2bv = pb[0], s2ev = pe[0];
    for (int idx = blockIdx.x * 512 + tid; idx < Q * Q / 4; idx += NCTA * 512) {
      int i  = idx >> 9;
      int j4 = idx & 511;
      int j = j4 * 4;
      int ci = g_cnt[i];
      int4 cj = *(const int4*)(g_cnt + j);
      float sci = sqrtf((float)ci) * s2bv;
      float4 d = *(const float4*)(dist + (size_t)i * Q + j);
      float4 o;
      o.x = sci * sqrtf((float)cj.x) * expf(-d.x * inv2l);
      o.y = sci * sqrtf((float)cj.y) * expf(-d.y * inv2l);
      o.z = sci * sqrtf((float)cj.z) * expf(-d.z * inv2l);
      o.w = sci * sqrtf((float)cj.w) * expf(-d.w * inv2l);
      if (i >= j && i < j + 4) ((float*)&o)[i - j] += s2ev;
      *(float4*)(g_A + (size_t)i * Q + j) = o;
      if (idx < Q) {
        int c = g_cnt[idx];
        g_v[idx] = (c > 0) ? g_w[idx] * rsqrtf((float)c) : 0.f;
      }
    }
  }
  grid_bar(bt);

  // ---- phase 3: Cholesky, 32 steps, ONE barrier per step ----
  #pragma unroll 1
  for (int step = 0; step < NSTEP; step++) {
    int k0 = step * NB2;
    potf64(ds, li, lg, k0, tid, warp, lane);
    if (blockIdx.x == 0) {
      for (int idx = tid; idx < 64 * 64; idx += 512) {
        int r = idx >> 6, c = idx & 63;
        if (c <= r) g_A[(size_t)(k0 + r) * Q + k0 + c] = ds[r * LP + c];
        g_Linv[step * 4096 + idx] = li[r * LP + c];
      }
      if (tid == 0) {
        double acc = 0.0;
        for (int j = 0; j < 64; j++) acc += (double)lg[j];
        atomicAdd(&g_red[2], acc);
      }
    }
    int nrows = Q - k0 - NB2;
    if (nrows > 0) {
      int nT = nrows >> 6;
      int njS = nT * (nT + 1) / 2;
      int t0 = k0 + NB2;
      for (int jj = blockIdx.x * 4 + team; jj < njS; jj += NCTA * 4) {
        int ti = (int)((sqrtf(8.f * (float)jj + 1.f) - 1.f) * 0.5f);
        while ((ti + 1) * (ti + 2) / 2 <= jj) ti++;
        while (ti * (ti + 1) / 2 > jj) ti--;
        int tj = jj - ti * (ti + 1) / 2;
        compute_X(k0, ti, as, xi, li, wtid, team, ti == tj);
        float* xjp = xi;
        if (ti != tj) { compute_X(k0, tj, as, xj, li, wtid, team, false); xjp = xj; }
        // syrk tile: A22[ti][tj] -= Xi * Xj^T (both k-major in smem)
        int tx = wtid & 15, ty = wtid >> 4;
        float acc[8][4] = {};
        #pragma unroll 4
        for (int k = 0; k < 64; k++) {
          float4 A0 = *(const float4*)&xi[k * LP + ty * 8];
          float4 A1 = *(const float4*)&xi[k * LP + ty * 8 + 4];
          float4 B0 = *(const float4*)&xjp[k * LP + tx * 4];
          float ar[8] = {A0.x, A0.y, A0.z, A0.w, A1.x, A1.y, A1.z, A1.w};
          float br[4] = {B0.x, B0.y, B0.z, B0.w};
          #pragma unroll
          for (int i = 0; i < 8; i++)
            #pragma unroll
            for (int j = 0; j < 4; j++)
              acc[i][j] += ar[i] * br[j];
        }
        #pragma unroll
        for (int i = 0; i < 8; i++) {
          float* cp = g_A + (size_t)(t0 + ti * 64 + ty * 8 + i) * Q + t0 + tj * 64 + tx * 4;
          float4 v = *(float4*)cp;
          v.x -= acc[i][0]; v.y -= acc[i][1]; v.z -= acc[i][2]; v.w -= acc[i][3];
          *(float4*)cp = v;
        }
      }
      grid_bar(bt);
    }
  }

  // ---- phase 4: forward solve + scalar (CTA0 only) ----
  if (blockIdx.x != 0) return;
  float* vbuf = sh;
  float* ybuf = sh + Q;
  double* dred = (double*)(sh + 2 * Q);
  __syncthreads();
  for (int i = tid; i < Q; i += 512) vbuf[i] = g_v[i];
  __syncthreads();

  double pv = 0.0;
  for (int i = tid; i < Q; i += 512) { double t = vbuf[i]; pv += t * t; }
  double vtv = block_reduce_512(pv, dred);

  int row = tid >> 3, l8 = tid & 7;
  for (int b = 0; b < NSTEP; b++) {
    int c0 = b * NB2;
    const float* Li = g_Linv + b * 4096;
    float4 a0 = *(const float4*)(Li + row * 64 + l8 * 8);
    float4 a1 = *(const float4*)(Li + row * 64 + l8 * 8 + 4);
    float4 v0 = *(const float4*)(&vbuf[c0 + l8 * 8]);
    float4 v1 = *(const float4*)(&vbuf[c0 + l8 * 8 + 4]);
    float acc = a0.x * v0.x + a0.y * v0.y + a0.z * v0.z + a0.w * v0.w
              + a1.x * v1.x + a1.y * v1.y + a1.z * v1.z + a1.w * v1.w;
    acc += __shfl_down_sync(0xffffffffu, acc, 4, 8);
    acc += __shfl_down_sync(0xffffffffu, acc, 2, 8);
    acc += __shfl_down_sync(0xffffffffu, acc, 1, 8);
    if (l8 == 0) ybuf[c0 + row] = acc;
    __syncthreads();
    // v_rest -= L21^T-column reads (coalesced across threads)
    for (int rb2 = c0 + NB2 + tid; rb2 < Q; rb2 += 512) {
      float acc2 = 0.f;
      const float* colp = g_A + (size_t)c0 * Q + rb2;
      #pragma unroll 8
      for (int k = 0; k < 64; k++)
        acc2 += colp[(size_t)k * Q] * ybuf[c0 + k];
      vbuf[rb2] -= acc2;
    }
    __syncthreads();
  }

  double py = 0.0;
  for (int i = tid; i < Q; i += 512) { double t = ybuf[i]; py += t * t; }
  double yty = block_reduce_512(py, dred);

  if (tid == 0) {
    double mtm = g_red[0], sumR2 = g_red[1], logdetA = 2.0 * g_red[2];
    double s2e = (double)pe[0], s2b = (double)pb[0], s2 = s2e + s2b;
    double dn = (double)n;
    double logdetR = (dn - (double)Q) * log(s2e) + logdetA - dn * log(s2);
    double mVm = (mtm - vtv + s2e * yty) / s2e;
    double slp = -0.5 * dn * log(6.283185307179586 * s2) - sumR2 / (2.0 * s2);
    double total = 0.5 * logdetR + 0.5 * s2 * mVm - 0.5 * mtm + 0.5 * slp;
    out[0] = (float)total;
  }
}

// ---------------- host ----------------
extern "C" void kernel_launch(void* const* d_in, const int* in_sizes, int n_in,
                              void* d_out, int out_size) {
  const float* y_true = (const float*)d_in[0];
  const float* y_pred = (const float*)d_in[1];
  const int*   Z_idx  = (const int*)  d_in[2];
  const float* dist   = (const float*)d_in[3];
  const float* s2e    = (const float*)d_in[4];
  const float* s2b    = (const float*)d_in[5];
  const float* ell    = (const float*)d_in[6];
  int n = in_sizes[0];

  // smem: ds + li + lg + 4 teams * (xi + xj + as) = 47936 floats = 191744 B
  size_t chol_smem = (size_t)(2 * 64 * LP + 64 + 4 * (2 * 64 * LP + 16 * LP)) * sizeof(float);
  cudaFuncSetAttribute(k_chol, cudaFuncAttributeMaxDynamicSharedMemorySize, (int)chol_smem);

  k_reset<<<(Q + 255) / 256, 256>>>();
  k_chol<<<NCTA, 512, chol_smem>>>(y_true, y_pred, Z_idx, dist,
                                   s2e, s2b, ell, (float*)d_out, n);
}

// round 14
// speedup vs baseline: 1.2413x; 1.2413x over previous
#include <cuda_runtime.h>
#include <cstdint>
#include <cstddef>

#define Q      2048
#define NB2    64
#define NSTEP  (Q/NB2)        // 32
#define NCTA   148
#define LP     68             // smem pitch for 64x64 tiles (float4-aligned)

// ---------------- scratch (device globals; no allocations allowed) ----------
__device__ float  g_A[Q*Q];                 // working matrix / Cholesky factor
__device__ float  g_Linv[NSTEP*NB2*NB2];    // per-step inverse of diag block (row-major 64)
__device__ float  g_w[Q];
__device__ int    g_cnt[Q];
__device__ float  g_v[Q];
__device__ double g_red[4];                 // [0]=m'm [1]=sum r^2 [2]=sum log Lkk
__device__ unsigned g_barCnt;               // grid barrier MONOTONIC arrival counter

extern __shared__ float sh[];

// ---------------- grid barrier: CG-style, thread0-only release/acquire ------
// NO per-thread __threadfence (that was 1024 MEMBAR.GPU per CTA per barrier).
// bar.sync gives intra-CTA happens-before; thread0's red.release/ld.acquire
// extends it to gpu scope via PTX cumulativity — the exact pattern
// cooperative_groups::grid_group::sync() emits.
__device__ __forceinline__ void grid_bar(unsigned &target) {
  __syncthreads();
  if (threadIdx.x == 0) {
    target += NCTA;
    asm volatile("red.release.gpu.global.add.u32 [%0], 1;"
                 :: "l"(&g_barCnt) : "memory");
    unsigned cur;
    do {
      asm volatile("ld.acquire.gpu.global.u32 %0, [%1];"
                   : "=r"(cur) : "l"(&g_barCnt) : "memory");
    } while (cur < target);
  }
  __syncthreads();
}

// ---------------- reductions ----------------
__device__ __forceinline__ double block_reduce_1024(double v, double* scratch) {
  #pragma unroll
  for (int o = 16; o; o >>= 1) v += __shfl_down_sync(0xffffffffu, v, o);
  if ((threadIdx.x & 31) == 0) scratch[threadIdx.x >> 5] = v;
  __syncthreads();
  double r = 0.0;
  if (threadIdx.x < 32) {
    r = scratch[threadIdx.x];
    #pragma unroll
    for (int o = 16; o; o >>= 1) r += __shfl_down_sync(0xffffffffu, r, o);
  }
  __syncthreads();
  return r;
}

// ---------------- small kernels ----------------
__global__ void k_reset() {
  int i = blockIdx.x * blockDim.x + threadIdx.x;
  if (i < Q) { g_w[i] = 0.f; g_cnt[i] = 0; }
  if (i < 4) g_red[i] = 0.0;
  if (i == 0) g_barCnt = 0u;
}

__global__ void k_obs(const float* __restrict__ yt, const float* __restrict__ yp,
                      const int* __restrict__ z,
                      const float* __restrict__ pe, const float* __restrict__ pb, int n) {
  int i = blockIdx.x * blockDim.x + threadIdx.x;
  float m = 0.f, r = 0.f;
  if (i < n) {
    r = yt[i] - yp[i];
    float s2 = pe[0] + pb[0];
    float u  = 0.5f * (erff(r / sqrtf(2.f * s2)) + 1.f);
    u = fminf(fmaxf(u, 1e-5f), 1.f - 1e-5f);
    m = erfinvf(2.f * u - 1.f) * 1.41421356237309515f;
    atomicAdd(&g_cnt[z[i]], 1);
    atomicAdd(&g_w[z[i]], m);
  }
  double mm = (double)m * (double)m;
  double rr = (double)r * (double)r;
  #pragma unroll
  for (int o = 16; o; o >>= 1) {
    mm += __shfl_down_sync(0xffffffffu, mm, o);
    rr += __shfl_down_sync(0xffffffffu, rr, o);
  }
  if ((threadIdx.x & 31) == 0) { atomicAdd(&g_red[0], mm); atomicAdd(&g_red[1], rr); }
}

__global__ void k_build(const float* __restrict__ dist, const float* __restrict__ pe,
                        const float* __restrict__ pb, const float* __restrict__ pl) {
  int idx = blockIdx.x * 256 + threadIdx.x;
  int i  = idx >> 9;
  int j4 = idx & 511;
  int j = j4 * 4;
  float inv2l = 0.5f / pl[0];
  int ci = g_cnt[i];
  int4 cj = *(const int4*)(g_cnt + j);
  float sci = sqrtf((float)ci) * pb[0];
  float4 d = *(const float4*)(dist + (size_t)i * Q + j);
  float4 o;
  o.x = sci * sqrtf((float)cj.x) * expf(-d.x * inv2l);
  o.y = sci * sqrtf((float)cj.y) * expf(-d.y * inv2l);
  o.z = sci * sqrtf((float)cj.z) * expf(-d.z * inv2l);
  o.w = sci * sqrtf((float)cj.w) * expf(-d.w * inv2l);
  if (i >= j && i < j + 4) ((float*)&o)[i - j] += pe[0];
  *(float4*)(g_A + (size_t)i * Q + j) = o;
  if (idx < Q) {
    int c = g_cnt[idx];
    g_v[idx] = (c > 0) ? g_w[idx] * rsqrtf((float)c) : 0.f;
  }
}

// ---------------- 32x32 register factor + inverse (warp 0 of each CTA) ------
__device__ __forceinline__ void fact32(float* ds, float* li, float* lg,
                                       int base, int lane) {
  float a[32];
  #pragma unroll
  for (int j = 0; j < 32; j++) a[j] = ds[(base + lane) * LP + base + j];
  #pragma unroll
  for (int j = 0; j < 32; j++) {
    float dj  = __shfl_sync(0xffffffffu, a[j], j);
    float d   = sqrtf(dj);
    float inv = 1.f / d;
    if (lane == j)     a[j] = d;
    else if (lane > j) a[j] *= inv;
    float lj = a[j];
    #pragma unroll
    for (int k = j + 1; k < 32; k++) {
      float Lkj = __shfl_sync(0xffffffffu, a[j], k);
      if (lane >= k) a[k] -= lj * Lkj;
    }
  }
  #pragma unroll
  for (int j = 0; j < 32; j++)
    if (j <= lane) ds[(base + lane) * LP + base + j] = a[j];
  lg[base + lane] = logf(a[lane]);
  // invert: lane = column of M = inv(L32)
  float dinvl = 1.f / a[lane];
  float x[32];
  #pragma unroll
  for (int r = 0; r < 32; r++) x[r] = (r == lane) ? 1.f : 0.f;
  #pragma unroll
  for (int k = 0; k < 32; k++) {
    float dk = __shfl_sync(0xffffffffu, dinvl, k);
    x[k] *= dk;
    float xk = x[k];
    #pragma unroll
    for (int r = k + 1; r < 32; r++) {
      float Lrk = __shfl_sync(0xffffffffu, a[k], r);
      x[r] -= Lrk * xk;
    }
  }
  #pragma unroll
  for (int r = 0; r < 32; r++)
    if (r >= lane) li[(base + r) * LP + base + lane] = x[r];
}

// ---------------- replicated 64x64 potf: L in ds, inv(L) in li, logs in lg --
__device__ void potf64(float* ds, float* li, float* lg, int k0,
                       int tid, int warp, int lane) {
  for (int idx = tid; idx < 64 * 64; idx += 512) {
    int r = idx >> 6, c = idx & 63;
    ds[r * LP + c] = g_A[(size_t)(k0 + r) * Q + k0 + c];
    li[r * LP + c] = 0.f;
  }
  __syncthreads();

  if (warp == 0) fact32(ds, li, lg, 0, lane);
  __syncthreads();

  // X = B * M1^T  (B = ds[32:64,0:32]) in place
  bool act = tid < 64;
  int ti = tid >> 3, tj = tid & 7;
  int r0 = 32 + ti * 4, m0 = tj * 4;
  float xa[4][4] = {};
  if (act) {
    #pragma unroll
    for (int k = 0; k < 32; k++) {
      float b0 = ds[(r0 + 0) * LP + k], b1 = ds[(r0 + 1) * LP + k];
      float b2 = ds[(r0 + 2) * LP + k], b3 = ds[(r0 + 3) * LP + k];
      float m0v = li[(m0 + 0) * LP + k], m1v = li[(m0 + 1) * LP + k];
      float m2v = li[(m0 + 2) * LP + k], m3v = li[(m0 + 3) * LP + k];
      xa[0][0] += b0 * m0v; xa[0][1] += b0 * m1v; xa[0][2] += b0 * m2v; xa[0][3] += b0 * m3v;
      xa[1][0] += b1 * m0v; xa[1][1] += b1 * m1v; xa[1][2] += b1 * m2v; xa[1][3] += b1 * m3v;
      xa[2][0] += b2 * m0v; xa[2][1] += b2 * m1v; xa[2][2] += b2 * m2v; xa[2][3] += b2 * m3v;
      xa[3][0] += b3 * m0v; xa[3][1] += b3 * m1v; xa[3][2] += b3 * m2v; xa[3][3] += b3 * m3v;
    }
  }
  __syncthreads();
  if (act) {
    #pragma unroll
    for (int i = 0; i < 4; i++)
      #pragma unroll
      for (int j = 0; j < 4; j++)
        ds[(r0 + i) * LP + tj * 4 + j] = xa[i][j];
  }
  __syncthreads();

  // S -= X*X^T (lower 4x4 tiles)
  if (tid < 36) {
    int di = 0;
    while ((di + 1) * (di + 2) / 2 <= tid) di++;
    int dj = tid - di * (di + 1) / 2;
    int tr = 32 + di * 4, tc = 32 + dj * 4;
    float a2[4][4] = {};
    #pragma unroll
    for (int k = 0; k < 32; k++) {
      float a0 = ds[(tr + 0) * LP + k], a1 = ds[(tr + 1) * LP + k];
      float aa2 = ds[(tr + 2) * LP + k], a3 = ds[(tr + 3) * LP + k];
      float b0 = ds[(tc + 0) * LP + k], b1 = ds[(tc + 1) * LP + k];
      float b2 = ds[(tc + 2) * LP + k], b3 = ds[(tc + 3) * LP + k];
      a2[0][0] += a0 * b0; a2[0][1] += a0 * b1; a2[0][2] += a0 * b2; a2[0][3] += a0 * b3;
      a2[1][0] += a1 * b0; a2[1][1] += a1 * b1; a2[1][2] += a1 * b2; a2[1][3] += a1 * b3;
      a2[2][0] += aa2 * b0; a2[2][1] += aa2 * b1; a2[2][2] += aa2 * b2; a2[2][3] += aa2 * b3;
      a2[3][0] += a3 * b0; a2[3][1] += a3 * b1; a2[3][2] += a3 * b2; a2[3][3] += a3 * b3;
    }
    #pragma unroll
    for (int i = 0; i < 4; i++)
      #pragma unroll
      for (int j = 0; j < 4; j++)
        ds[(tr + i) * LP + tc + j] -= a2[i][j];
  }
  __syncthreads();

  if (warp == 0) fact32(ds, li, lg, 32, lane);
  __syncthreads();

  // T = L21 * M1 -> scratch li[0:32, 32:64]
  for (int t = tid; t < 1024; t += 512) {
    int i = t >> 5, j = t & 31;
    float acc = 0.f;
    #pragma unroll 8
    for (int k = 0; k < 32; k++)
      acc += ds[(32 + i) * LP + k] * li[k * LP + j];
    li[i * LP + 32 + j] = acc;
  }
  __syncthreads();
  // M21 = -M2 * T -> li[32:64, 0:32]
  for (int t = tid; t < 1024; t += 512) {
    int i = t >> 5, j = t & 31;
    float acc = 0.f;
    #pragma unroll 8
    for (int k = 0; k < 32; k++)
      acc += li[(32 + i) * LP + 32 + k] * li[k * LP + 32 + j];
    li[(32 + i) * LP + j] = -acc;
  }
  __syncthreads();
  // zero scratch region (Linv upper must be 0)
  for (int t = tid; t < 1024; t += 512) {
    int i = t >> 5, j = t & 31;
    li[i * LP + 32 + j] = 0.f;
  }
  __syncthreads();
}

// ---------------- 64x64 syrk GEMM core (K=64), 128-thread team --------------
__device__ __forceinline__ void team_bar(int team) {
  asm volatile("bar.sync %0, 128;" :: "r"(team + 4) : "memory");
}

__device__ __forceinline__ void gemm64_k64(const float* __restrict__ aRow,
                                           const float* __restrict__ bRow,
                                           float* as, float* bs, int wtid, int team,
                                           float acc[8][4]) {
  int tx = wtid & 15, ty = wtid >> 4;
  for (int kk = 0; kk < 64; kk += 16) {
    #pragma unroll
    for (int i2 = 0; i2 < 2; i2++) {
      int li2 = wtid + i2 * 128;
      int r = li2 >> 2, c4 = li2 & 3;
      float4 va = *(const float4*)(aRow + (size_t)r * Q + kk + c4 * 4);
      float4 vb = *(const float4*)(bRow + (size_t)r * Q + kk + c4 * 4);
      as[(c4 * 4 + 0) * 68 + r] = va.x; as[(c4 * 4 + 1) * 68 + r] = va.y;
      as[(c4 * 4 + 2) * 68 + r] = va.z; as[(c4 * 4 + 3) * 68 + r] = va.w;
      bs[(c4 * 4 + 0) * 68 + r] = vb.x; bs[(c4 * 4 + 1) * 68 + r] = vb.y;
      bs[(c4 * 4 + 2) * 68 + r] = vb.z; bs[(c4 * 4 + 3) * 68 + r] = vb.w;
    }
    team_bar(team);
    #pragma unroll
    for (int k = 0; k < 16; k++) {
      float4 A0 = *(const float4*)&as[k * 68 + ty * 8];
      float4 A1 = *(const float4*)&as[k * 68 + ty * 8 + 4];
      float4 B0 = *(const float4*)&bs[k * 68 + tx * 4];
      float ar[8] = {A0.x, A0.y, A0.z, A0.w, A1.x, A1.y, A1.z, A1.w};
      float br[4] = {B0.x, B0.y, B0.z, B0.w};
      #pragma unroll
      for (int i = 0; i < 8; i++)
        #pragma unroll
        for (int j = 0; j < 4; j++)
          acc[i][j] += ar[i] * br[j];
    }
    team_bar(team);
  }
}

// ---------------- persistent Cholesky: 32 steps of width 64 -----------------
__global__ void __launch_bounds__(512, 1) k_chol() {
  int tid  = threadIdx.x;
  int warp = tid >> 5, lane = tid & 31;
  int team = tid >> 7, wtid = tid & 127;
  float* ds = sh;                       // 64*68
  float* li = sh + 64 * LP;             // 64*68
  float* lg = sh + 2 * 64 * LP;         // 64
  float* as = sh + 2 * 64 * LP + 64 + team * 2 * 16 * 68;
  float* bs = as + 16 * 68;
  unsigned bt = 0;

  #pragma unroll 1
  for (int step = 0; step < NSTEP; step++) {
    int k0 = step * NB2;
    potf64(ds, li, lg, k0, tid, warp, lane);
    int nrows = Q - k0 - NB2;

    // ---- trsm: L21 rows = A21 * Linv^T (Linv in LOCAL smem), 16-row chunks --
    if (nrows > 0) {
      int nch = nrows >> 4;
      for (int j = blockIdx.x * 4 + team; j < nch; j += NCTA * 4) {
        int r0 = k0 + NB2 + j * 16;
        #pragma unroll
        for (int u = 0; u < 2; u++) {
          int t2 = wtid + u * 128;
          int r = t2 >> 4, c4 = t2 & 15;
          float4 va = *(const float4*)(g_A + (size_t)(r0 + r) * Q + k0 + c4 * 4);
          *(float4*)(as + r * 68 + c4 * 4) = va;
        }
        team_bar(team);
        int row = wtid & 15, cg = wtid >> 4;
        float acc[8] = {};
        #pragma unroll
        for (int k4 = 0; k4 < 16; k4++) {
          float4 a4 = *(const float4*)(as + row * 68 + k4 * 4);
          #pragma unroll
          for (int c = 0; c < 8; c++) {
            float4 m4 = *(const float4*)(li + (cg * 8 + c) * LP + k4 * 4);
            acc[c] += a4.x * m4.x + a4.y * m4.y + a4.z * m4.z + a4.w * m4.w;
          }
        }
        float* dst = g_A + (size_t)(r0 + row) * Q + k0 + cg * 8;
        *(float4*)dst       = make_float4(acc[0], acc[1], acc[2], acc[3]);
        *(float4*)(dst + 4) = make_float4(acc[4], acc[5], acc[6], acc[7]);
        team_bar(team);
      }
    }
    grid_bar(bt);

    // CTA0 persists diag L, Linv, logdet
    if (blockIdx.x == 0) {
      for (int idx = tid; idx < 64 * 64; idx += 512) {
        int r = idx >> 6, c = idx & 63;
        if (c <= r) g_A[(size_t)(k0 + r) * Q + k0 + c] = ds[r * LP + c];
        g_Linv[step * 4096 + idx] = li[r * LP + c];
      }
      if (tid == 0) {
        double acc = 0.0;
        for (int j = 0; j < 64; j++) acc += (double)lg[j];
        atomicAdd(&g_red[2], acc);
      }
    }

    // ---- syrk: A22 -= L21 * L21^T (lower 64-tiles, K=64) --------------------
    if (nrows > 0) {
      int nT = nrows >> 6;
      int njS = nT * (nT + 1) / 2;
      int t0 = k0 + NB2;
      for (int j = blockIdx.x * 4 + team; j < njS; j += NCTA * 4) {
        int ti = (int)((sqrtf(8.f * (float)j + 1.f) - 1.f) * 0.5f);
        while ((ti + 1) * (ti + 2) / 2 <= j) ti++;
        while (ti * (ti + 1) / 2 > j) ti--;
        int tj = j - ti * (ti + 1) / 2;
        const float* aRow = g_A + (size_t)(t0 + ti * 64) * Q + k0;
        const float* bRow = g_A + (size_t)(t0 + tj * 64) * Q + k0;
        float acc[8][4] = {};
        gemm64_k64(aRow, bRow, as, bs, wtid, team, acc);
        int tx = wtid & 15, ty = wtid >> 4;
        #pragma unroll
        for (int i = 0; i < 8; i++) {
          float* cp = g_A + (size_t)(t0 + ti * 64 + ty * 8 + i) * Q + t0 + tj * 64 + tx * 4;
          float4 v = *(float4*)cp;
          v.x -= acc[i][0]; v.y -= acc[i][1]; v.z -= acc[i][2]; v.w -= acc[i][3];
          *(float4*)cp = v;
        }
      }
    }
    grid_bar(bt);
  }
}

// ---------------- forward solve + final assembly (single CTA, 1024 thr) ----
__global__ void k_solve(float* __restrict__ out, const float* __restrict__ pe,
                        const float* __restrict__ pb, int n) {
  float* vbuf = sh;         // Q
  float* ybuf = sh + Q;     // Q
  __shared__ double dred[32];
  int tid = threadIdx.x;

  for (int i = tid; i < Q; i += 1024) vbuf[i] = g_v[i];
  __syncthreads();

  double pv = 0.0;
  for (int i = tid; i < Q; i += 1024) { double t = vbuf[i]; pv += t * t; }
  double vtv = block_reduce_1024(pv, dred);

  int row16 = tid >> 4, l16 = tid & 15;
  int w = tid >> 5, lane = tid & 31;
  int rsub = lane >> 3, jj = lane & 7;

  for (int b = 0; b < NSTEP; b++) {
    int c0 = b * NB2;
    const float* Li = g_Linv + b * 4096;
    float4 a = *(const float4*)(Li + row16 * 64 + l16 * 4);
    float4 v = *(const float4*)(&vbuf[c0 + l16 * 4]);
    float acc = a.x * v.x + a.y * v.y + a.z * v.z + a.w * v.w;
    #pragma unroll
    for (int o = 8; o; o >>= 1) acc += __shfl_down_sync(0xffffffffu, acc, o, 16);
    if (l16 == 0) ybuf[c0 + row16] = acc;
    __syncthreads();

    const float4* Yb = (const float4*)&ybuf[c0];
    float4 yr0 = Yb[jj], yr1 = Yb[jj + 8];
    #pragma unroll 2
    for (int r4 = c0 + NB2 + w * 4; r4 < Q; r4 += 128) {
      int r = r4 + rsub;
      const float4* Ar = (const float4*)&g_A[(size_t)r * Q + c0];
      float4 a0 = Ar[jj], a1 = Ar[jj + 8];
      float s = a0.x * yr0.x + a0.y * yr0.y + a0.z * yr0.z + a0.w * yr0.w
              + a1.x * yr1.x + a1.y * yr1.y + a1.z * yr1.z + a1.w * yr1.w;
      s += __shfl_down_sync(0xffffffffu, s, 4, 8);
      s += __shfl_down_sync(0xffffffffu, s, 2, 8);
      s += __shfl_down_sync(0xffffffffu, s, 1, 8);
      if (jj == 0) vbuf[r] -= s;
    }
    __syncthreads();
  }

  double py = 0.0;
  for (int i = tid; i < Q; i += 1024) { double t = ybuf[i]; py += t * t; }
  double yty = block_reduce_1024(py, dred);

  if (tid == 0) {
    double mtm = g_red[0], sumR2 = g_red[1], logdetA = 2.0 * g_red[2];
    double s2e = (double)pe[0], s2b = (double)pb[0], s2 = s2e + s2b;
    double dn = (double)n;
    double logdetR = (dn - (double)Q) * log(s2e) + logdetA - dn * log(s2);
    double mVm = (mtm - vtv + s2e * yty) / s2e;
    double slp = -0.5 * dn * log(6.283185307179586 * s2) - sumR2 / (2.0 * s2);
    double total = 0.5 * logdetR + 0.5 * s2 * mVm - 0.5 * mtm + 0.5 * slp;
    out[0] = (float)total;
  }
}

// ---------------- host ----------------
extern "C" void kernel_launch(void* const* d_in, const int* in_sizes, int n_in,
                              void* d_out, int out_size) {
  const float* y_true = (const float*)d_in[0];
  const float* y_pred = (const float*)d_in[1];
  const int*   Z_idx  = (const int*)  d_in[2];
  const float* dist   = (const float*)d_in[3];
  const float* s2e    = (const float*)d_in[4];
  const float* s2b    = (const float*)d_in[5];
  const float* ell    = (const float*)d_in[6];
  int n = in_sizes[0];

  size_t chol_smem  = (size_t)(2 * 64 * LP + 64 + 4 * 2 * 16 * 68) * sizeof(float); // ~68.3 KB
  size_t solve_smem = (size_t)(2 * Q) * sizeof(float);
  cudaFuncSetAttribute(k_chol,  cudaFuncAttributeMaxDynamicSharedMemorySize, (int)chol_smem);
  cudaFuncSetAttribute(k_solve, cudaFuncAttributeMaxDynamicSharedMemorySize, (int)solve_smem);

  k_reset<<<(Q + 255) / 256, 256>>>();                                   // launch 0
  k_obs<<<(n + 255) / 256, 256>>>(y_true, y_pred, Z_idx, s2e, s2b, n);   // launch 1
  k_build<<<(Q * Q / 4) / 256, 256>>>(dist, s2e, s2b, ell);              // launch 2
  k_chol<<<NCTA, 512, chol_smem>>>();                                    // launch 3 (ncu slot)
  k_solve<<<1, 1024, solve_smem>>>((float*)d_out, s2e, s2b, n);          // launch 4
}

// round 15
// speedup vs baseline: 1.2897x; 1.0390x over previous
#include <cuda_runtime.h>
#include <cstdint>
#include <cstddef>

#define Q      2048
#define NB2    64
#define NSTEP  (Q/NB2)        // 32
#define NCTA   148
#define LP     68             // smem pitch for 64x64 tiles (float4-aligned)
#define NTHR   256            // k_chol threads (despill: 255-reg budget)

// ---------------- scratch (device globals; no allocations allowed) ----------
__device__ float  g_A[Q*Q];                 // working matrix / Cholesky factor
__device__ float  g_Linv[NSTEP*NB2*NB2];    // per-step inverse of diag block
__device__ float  g_w[Q];
__device__ int    g_cnt[Q];
__device__ float  g_v[Q];
__device__ double g_red[4];                 // [0]=m'm [1]=sum r^2 [2]=sum log Lkk
__device__ unsigned g_barCnt;               // grid barrier MONOTONIC arrival counter

extern __shared__ float sh[];

// ---------------- grid barrier: CG-style, thread0-only release/acquire ------
__device__ __forceinline__ void grid_bar(unsigned &target) {
  __syncthreads();
  if (threadIdx.x == 0) {
    target += NCTA;
    asm volatile("red.release.gpu.global.add.u32 [%0], 1;"
                 :: "l"(&g_barCnt) : "memory");
    unsigned cur;
    do {
      asm volatile("ld.acquire.gpu.global.u32 %0, [%1];"
                   : "=r"(cur) : "l"(&g_barCnt) : "memory");
    } while (cur < target);
  }
  __syncthreads();
}

// ---------------- reductions ----------------
__device__ __forceinline__ double block_reduce_1024(double v, double* scratch) {
  #pragma unroll
  for (int o = 16; o; o >>= 1) v += __shfl_down_sync(0xffffffffu, v, o);
  if ((threadIdx.x & 31) == 0) scratch[threadIdx.x >> 5] = v;
  __syncthreads();
  double r = 0.0;
  if (threadIdx.x < 32) {
    r = scratch[threadIdx.x];
    #pragma unroll
    for (int o = 16; o; o >>= 1) r += __shfl_down_sync(0xffffffffu, r, o);
  }
  __syncthreads();
  return r;
}

// ---------------- small kernels ----------------
__global__ void k_reset() {
  int i = blockIdx.x * blockDim.x + threadIdx.x;
  if (i < Q) { g_w[i] = 0.f; g_cnt[i] = 0; }
  if (i < 4) g_red[i] = 0.0;
  if (i == 0) g_barCnt = 0u;
}

__global__ void k_obs(const float* __restrict__ yt, const float* __restrict__ yp,
                      const int* __restrict__ z,
                      const float* __restrict__ pe, const float* __restrict__ pb, int n) {
  int i = blockIdx.x * blockDim.x + threadIdx.x;
  float m = 0.f, r = 0.f;
  if (i < n) {
    r = yt[i] - yp[i];
    float s2 = pe[0] + pb[0];
    float u  = 0.5f * (erff(r / sqrtf(2.f * s2)) + 1.f);
    u = fminf(fmaxf(u, 1e-5f), 1.f - 1e-5f);
    m = erfinvf(2.f * u - 1.f) * 1.41421356237309515f;
    atomicAdd(&g_cnt[z[i]], 1);
    atomicAdd(&g_w[z[i]], m);
  }
  double mm = (double)m * (double)m;
  double rr = (double)r * (double)r;
  #pragma unroll
  for (int o = 16; o; o >>= 1) {
    mm += __shfl_down_sync(0xffffffffu, mm, o);
    rr += __shfl_down_sync(0xffffffffu, rr, o);
  }
  if ((threadIdx.x & 31) == 0) { atomicAdd(&g_red[0], mm); atomicAdd(&g_red[1], rr); }
}

__global__ void k_build(const float* __restrict__ dist, const float* __restrict__ pe,
                        const float* __restrict__ pb, const float* __restrict__ pl) {
  int idx = blockIdx.x * 256 + threadIdx.x;
  int i  = idx >> 9;
  int j4 = idx & 511;
  int j = j4 * 4;
  float inv2l = 0.5f / pl[0];
  int ci = g_cnt[i];
  int4 cj = *(const int4*)(g_cnt + j);
  float sci = sqrtf((float)ci) * pb[0];
  float4 d = *(const float4*)(dist + (size_t)i * Q + j);
  float4 o;
  o.x = sci * sqrtf((float)cj.x) * expf(-d.x * inv2l);
  o.y = sci * sqrtf((float)cj.y) * expf(-d.y * inv2l);
  o.z = sci * sqrtf((float)cj.z) * expf(-d.z * inv2l);
  o.w = sci * sqrtf((float)cj.w) * expf(-d.w * inv2l);
  if (i >= j && i < j + 4) ((float*)&o)[i - j] += pe[0];
  *(float4*)(g_A + (size_t)i * Q + j) = o;
  if (idx < Q) {
    int c = g_cnt[idx];
    g_v[idx] = (c > 0) ? g_w[idx] * rsqrtf((float)c) : 0.f;
  }
}

// ---------------- 32x32 register factor + inverse (warp 0 of each CTA) ------
__device__ __forceinline__ void fact32(float* ds, float* li, float* lg,
                                       int base, int lane) {
  float a[32];
  #pragma unroll
  for (int j = 0; j < 32; j++) a[j] = ds[(base + lane) * LP + base + j];
  #pragma unroll
  for (int j = 0; j < 32; j++) {
    float dj  = __shfl_sync(0xffffffffu, a[j], j);
    float d   = sqrtf(dj);
    float inv = 1.f / d;
    if (lane == j)     a[j] = d;
    else if (lane > j) a[j] *= inv;
    float lj = a[j];
    #pragma unroll
    for (int k = j + 1; k < 32; k++) {
      float Lkj = __shfl_sync(0xffffffffu, a[j], k);
      if (lane >= k) a[k] -= lj * Lkj;
    }
  }
  #pragma unroll
  for (int j = 0; j < 32; j++)
    if (j <= lane) ds[(base + lane) * LP + base + j] = a[j];
  lg[base + lane] = logf(a[lane]);
  // invert: lane = column of M = inv(L32)
  float dinvl = 1.f / a[lane];
  float x[32];
  #pragma unroll
  for (int r = 0; r < 32; r++) x[r] = (r == lane) ? 1.f : 0.f;
  #pragma unroll
  for (int k = 0; k < 32; k++) {
    float dk = __shfl_sync(0xffffffffu, dinvl, k);
    x[k] *= dk;
    float xk = x[k];
    #pragma unroll
    for (int r = k + 1; r < 32; r++) {
      float Lrk = __shfl_sync(0xffffffffu, a[k], r);
      x[r] -= Lrk * xk;
    }
  }
  #pragma unroll
  for (int r = 0; r < 32; r++)
    if (r >= lane) li[(base + r) * LP + base + lane] = x[r];
}

// ---------------- replicated 64x64 potf (every CTA), 256 threads ------------
__device__ void potf64(float* ds, float* li, float* lg, int k0,
                       int tid, int warp, int lane) {
  for (int idx = tid; idx < 64 * 64; idx += NTHR) {
    int r = idx >> 6, c = idx & 63;
    ds[r * LP + c] = g_A[(size_t)(k0 + r) * Q + k0 + c];
    li[r * LP + c] = 0.f;
  }
  __syncthreads();

  if (warp == 0) fact32(ds, li, lg, 0, lane);
  __syncthreads();

  // X = B * M1^T  (B = ds[32:64, 0:32]), 256 threads: each 4 outputs in a row
  {
    int r32 = tid >> 3;            // 0..31
    int c0  = (tid & 7) * 4;       // 0,4,..,28
    float acc[4] = {};
    #pragma unroll
    for (int k = 0; k < 32; k++) {
      float b = ds[(32 + r32) * LP + k];
      acc[0] += b * li[(c0 + 0) * LP + k];
      acc[1] += b * li[(c0 + 1) * LP + k];
      acc[2] += b * li[(c0 + 2) * LP + k];
      acc[3] += b * li[(c0 + 3) * LP + k];
    }
    __syncthreads();
    ds[(32 + r32) * LP + c0 + 0] = acc[0];
    ds[(32 + r32) * LP + c0 + 1] = acc[1];
    ds[(32 + r32) * LP + c0 + 2] = acc[2];
    ds[(32 + r32) * LP + c0 + 3] = acc[3];
    __syncthreads();
  }

  // S22 -= X*X^T : lower 2x2 tiles (136 tiles, 136 threads)
  if (tid < 136) {
    int di = 0;
    while ((di + 1) * (di + 2) / 2 <= tid) di++;
    int dj = tid - di * (di + 1) / 2;
    int tr = 32 + di * 2, tc = 32 + dj * 2;
    float a00 = 0.f, a01 = 0.f, a10 = 0.f, a11 = 0.f;
    #pragma unroll
    for (int k = 0; k < 32; k++) {
      float x0 = ds[(tr + 0) * LP + k], x1 = ds[(tr + 1) * LP + k];
      float y0 = ds[(tc + 0) * LP + k], y1 = ds[(tc + 1) * LP + k];
      a00 += x0 * y0; a01 += x0 * y1; a10 += x1 * y0; a11 += x1 * y1;
    }
    ds[(tr + 0) * LP + tc + 0] -= a00;
    ds[(tr + 0) * LP + tc + 1] -= a01;
    ds[(tr + 1) * LP + tc + 0] -= a10;
    ds[(tr + 1) * LP + tc + 1] -= a11;
  }
  __syncthreads();

  if (warp == 0) fact32(ds, li, lg, 32, lane);
  __syncthreads();

  // T = L21 * M1 -> scratch li[0:32, 32:64]
  for (int t = tid; t < 1024; t += NTHR) {
    int i = t >> 5, j = t & 31;
    float acc = 0.f;
    #pragma unroll 8
    for (int k = 0; k < 32; k++)
      acc += ds[(32 + i) * LP + k] * li[k * LP + j];
    li[i * LP + 32 + j] = acc;
  }
  __syncthreads();
  // M21 = -M2 * T -> li[32:64, 0:32]
  for (int t = tid; t < 1024; t += NTHR) {
    int i = t >> 5, j = t & 31;
    float acc = 0.f;
    #pragma unroll 8
    for (int k = 0; k < 32; k++)
      acc += li[(32 + i) * LP + 32 + k] * li[k * LP + 32 + j];
    li[(32 + i) * LP + j] = -acc;
  }
  __syncthreads();
  // zero scratch region (Linv upper must be 0)
  for (int t = tid; t < 1024; t += NTHR) {
    int i = t >> 5, j = t & 31;
    li[i * LP + 32 + j] = 0.f;
  }
  __syncthreads();
}

// ---------------- 64x64 syrk GEMM core (K=64), 128-thread team --------------
__device__ __forceinline__ void team_bar(int team) {
  asm volatile("bar.sync %0, 128;" :: "r"(team + 4) : "memory");
}

__device__ __forceinline__ void gemm64_k64(const float* __restrict__ aRow,
                                           const float* __restrict__ bRow,
                                           float* as, float* bs, int wtid, int team,
                                           float acc[8][4]) {
  int tx = wtid & 15, ty = wtid >> 4;
  for (int kk = 0; kk < 64; kk += 16) {
    #pragma unroll
    for (int i2 = 0; i2 < 2; i2++) {
      int li2 = wtid + i2 * 128;
      int r = li2 >> 2, c4 = li2 & 3;
      float4 va = *(const float4*)(aRow + (size_t)r * Q + kk + c4 * 4);
      float4 vb = *(const float4*)(bRow + (size_t)r * Q + kk + c4 * 4);
      as[(c4 * 4 + 0) * 68 + r] = va.x; as[(c4 * 4 + 1) * 68 + r] = va.y;
      as[(c4 * 4 + 2) * 68 + r] = va.z; as[(c4 * 4 + 3) * 68 + r] = va.w;
      bs[(c4 * 4 + 0) * 68 + r] = vb.x; bs[(c4 * 4 + 1) * 68 + r] = vb.y;
      bs[(c4 * 4 + 2) * 68 + r] = vb.z; bs[(c4 * 4 + 3) * 68 + r] = vb.w;
    }
    team_bar(team);
    #pragma unroll
    for (int k = 0; k < 16; k++) {
      float4 A0 = *(const float4*)&as[k * 68 + ty * 8];
      float4 A1 = *(const float4*)&as[k * 68 + ty * 8 + 4];
      float4 B0 = *(const float4*)&bs[k * 68 + tx * 4];
      float ar[8] = {A0.x, A0.y, A0.z, A0.w, A1.x, A1.y, A1.z, A1.w};
      float br[4] = {B0.x, B0.y, B0.z, B0.w};
      #pragma unroll
      for (int i = 0; i < 8; i++)
        #pragma unroll
        for (int j = 0; j < 4; j++)
          acc[i][j] += ar[i] * br[j];
    }
    team_bar(team);
  }
}

// ---------------- persistent Cholesky: 32 steps, 256 threads/CTA ------------
__global__ void __launch_bounds__(NTHR, 1) k_chol() {
  int tid  = threadIdx.x;
  int warp = tid >> 5, lane = tid & 31;
  int team = tid >> 7, wtid = tid & 127;      // 2 teams of 128
  float* ds = sh;                       // 64*LP
  float* li = sh + 64 * LP;             // 64*LP
  float* lg = sh + 2 * 64 * LP;         // 64
  float* as = sh + 2 * 64 * LP + 64 + team * 2 * 16 * 68;
  float* bs = as + 16 * 68;
  unsigned bt = 0;

  #pragma unroll 1
  for (int step = 0; step < NSTEP; step++) {
    int k0 = step * NB2;
    potf64(ds, li, lg, k0, tid, warp, lane);
    int nrows = Q - k0 - NB2;

    // ---- trsm: L21 rows = A21 * Linv^T (Linv in LOCAL smem), 16-row chunks --
    if (nrows > 0) {
      int nch = nrows >> 4;
      for (int j = blockIdx.x * 2 + team; j < nch; j += NCTA * 2) {
        int r0 = k0 + NB2 + j * 16;
        #pragma unroll
        for (int u = 0; u < 2; u++) {
          int t2 = wtid + u * 128;
          int r = t2 >> 4, c4 = t2 & 15;
          float4 va = *(const float4*)(g_A + (size_t)(r0 + r) * Q + k0 + c4 * 4);
          *(float4*)(as + r * 68 + c4 * 4) = va;
        }
        team_bar(team);
        int row = wtid & 15, cg = wtid >> 4;
        float acc[8] = {};
        #pragma unroll
        for (int k4 = 0; k4 < 16; k4++) {
          float4 a4 = *(const float4*)(as + row * 68 + k4 * 4);
          #pragma unroll
          for (int c = 0; c < 8; c++) {
            float4 m4 = *(const float4*)(li + (cg * 8 + c) * LP + k4 * 4);
            acc[c] += a4.x * m4.x + a4.y * m4.y + a4.z * m4.z + a4.w * m4.w;
          }
        }
        float* dst = g_A + (size_t)(r0 + row) * Q + k0 + cg * 8;
        *(float4*)dst       = make_float4(acc[0], acc[1], acc[2], acc[3]);
        *(float4*)(dst + 4) = make_float4(acc[4], acc[5], acc[6], acc[7]);
        team_bar(team);
      }
    }
    grid_bar(bt);

    // CTA0 persists diag L, Linv, logdet
    if (blockIdx.x == 0) {
      for (int idx = tid; idx < 64 * 64; idx += NTHR) {
        int r = idx >> 6, c = idx & 63;
        if (c <= r) g_A[(size_t)(k0 + r) * Q + k0 + c] = ds[r * LP + c];
        g_Linv[step * 4096 + idx] = li[r * LP + c];
      }
      if (tid == 0) {
        double acc = 0.0;
        for (int j = 0; j < 64; j++) acc += (double)lg[j];
        atomicAdd(&g_red[2], acc);
      }
    }

    // ---- syrk: A22 -= L21 * L21^T (lower 64-tiles, K=64) --------------------
    if (nrows > 0) {
      int nT = nrows >> 6;
      int njS = nT * (nT + 1) / 2;
      int t0 = k0 + NB2;
      for (int j = blockIdx.x * 2 + team; j < njS; j += NCTA * 2) {
        int ti = (int)((sqrtf(8.f * (float)j + 1.f) - 1.f) * 0.5f);
        while ((ti + 1) * (ti + 2) / 2 <= j) ti++;
        while (ti * (ti + 1) / 2 > j) ti--;
        int tj = j - ti * (ti + 1) / 2;
        const float* aRow = g_A + (size_t)(t0 + ti * 64) * Q + k0;
        const float* bRow = g_A + (size_t)(t0 + tj * 64) * Q + k0;
        float acc[8][4] = {};
        gemm64_k64(aRow, bRow, as, bs, wtid, team, acc);
        int tx = wtid & 15, ty = wtid >> 4;
        #pragma unroll
        for (int i = 0; i < 8; i++) {
          float* cp = g_A + (size_t)(t0 + ti * 64 + ty * 8 + i) * Q + t0 + tj * 64 + tx * 4;
          float4 v = *(float4*)cp;
          v.x -= acc[i][0]; v.y -= acc[i][1]; v.z -= acc[i][2]; v.w -= acc[i][3];
          *(float4*)cp = v;
        }
      }
    }
    grid_bar(bt);
  }
}

// ---------------- forward solve + final assembly (single CTA, 1024 thr) ----
__global__ void k_solve(float* __restrict__ out, const float* __restrict__ pe,
                        const float* __restrict__ pb, int n) {
  float* vbuf = sh;         // Q
  float* ybuf = sh + Q;     // Q
  __shared__ double dred[32];
  int tid = threadIdx.x;

  for (int i = tid; i < Q; i += 1024) vbuf[i] = g_v[i];
  __syncthreads();

  double pv = 0.0;
  for (int i = tid; i < Q; i += 1024) { double t = vbuf[i]; pv += t * t; }
  double vtv = block_reduce_1024(pv, dred);

  int row16 = tid >> 4, l16 = tid & 15;
  int w = tid >> 5, lane = tid & 31;
  int rsub = lane >> 3, jj = lane & 7;

  for (int b = 0; b < NSTEP; b++) {
    int c0 = b * NB2;
    const float* Li = g_Linv + b * 4096;
    float4 a = *(const float4*)(Li + row16 * 64 + l16 * 4);
    float4 v = *(const float4*)(&vbuf[c0 + l16 * 4]);
    float acc = a.x * v.x + a.y * v.y + a.z * v.z + a.w * v.w;
    #pragma unroll
    for (int o = 8; o; o >>= 1) acc += __shfl_down_sync(0xffffffffu, acc, o, 16);
    if (l16 == 0) ybuf[c0 + row16] = acc;
    __syncthreads();

    const float4* Yb = (const float4*)&ybuf[c0];
    float4 yr0 = Yb[jj], yr1 = Yb[jj + 8];
    #pragma unroll 2
    for (int r4 = c0 + NB2 + w * 4; r4 < Q; r4 += 128) {
      int r = r4 + rsub;
      const float4* Ar = (const float4*)&g_A[(size_t)r * Q + c0];
      float4 a0 = Ar[jj], a1 = Ar[jj + 8];
      float s = a0.x * yr0.x + a0.y * yr0.y + a0.z * yr0.z + a0.w * yr0.w
              + a1.x * yr1.x + a1.y * yr1.y + a1.z * yr1.z + a1.w * yr1.w;
      s += __shfl_down_sync(0xffffffffu, s, 4, 8);
      s += __shfl_down_sync(0xffffffffu, s, 2, 8);
      s += __shfl_down_sync(0xffffffffu, s, 1, 8);
      if (jj == 0) vbuf[r] -= s;
    }
    __syncthreads();
  }

  double py = 0.0;
  for (int i = tid; i < Q; i += 1024) { double t = ybuf[i]; py += t * t; }
  double yty = block_reduce_1024(py, dred);

  if (tid == 0) {
    double mtm = g_red[0], sumR2 = g_red[1], logdetA = 2.0 * g_red[2];
    double s2e = (double)pe[0], s2b = (double)pb[0], s2 = s2e + s2b;
    double dn = (double)n;
    double logdetR = (dn - (double)Q) * log(s2e) + logdetA - dn * log(s2);
    double mVm = (mtm - vtv + s2e * yty) / s2e;
    double slp = -0.5 * dn * log(6.283185307179586 * s2) - sumR2 / (2.0 * s2);
    double total = 0.5 * logdetR + 0.5 * s2 * mVm - 0.5 * mtm + 0.5 * slp;
    out[0] = (float)total;
  }
}

// ---------------- host ----------------
extern "C" void kernel_launch(void* const* d_in, const int* in_sizes, int n_in,
                              void* d_out, int out_size) {
  const float* y_true = (const float*)d_in[0];
  const float* y_pred = (const float*)d_in[1];
  const int*   Z_idx  = (const int*)  d_in[2];
  const float* dist   = (const float*)d_in[3];
  const float* s2e    = (const float*)d_in[4];
  const float* s2b    = (const float*)d_in[5];
  const float* ell    = (const float*)d_in[6];
  int n = in_sizes[0];

  size_t chol_smem  = (size_t)(2 * 64 * LP + 64 + 2 * 2 * 16 * 68) * sizeof(float); // ~52.5 KB
  size_t solve_smem = (size_t)(2 * Q) * sizeof(float);
  cudaFuncSetAttribute(k_chol,  cudaFuncAttributeMaxDynamicSharedMemorySize, (int)chol_smem);
  cudaFuncSetAttribute(k_solve, cudaFuncAttributeMaxDynamicSharedMemorySize, (int)solve_smem);

  k_reset<<<(Q + 255) / 256, 256>>>();                                   // launch 0
  k_obs<<<(n + 255) / 256, 256>>>(y_true, y_pred, Z_idx, s2e, s2b, n);   // launch 1
  k_build<<<(Q * Q / 4) / 256, 256>>>(dist, s2e, s2b, ell);              // launch 2
  k_chol<<<NCTA, NTHR, chol_smem>>>();                                   // launch 3 (ncu slot)
  k_solve<<<1, 1024, solve_smem>>>((float*)d_out, s2e, s2b, n);          // launch 4
}